// round 2
// baseline (speedup 1.0000x reference)
#include <cuda_runtime.h>
#include <cuda_bf16.h>
#include <cstdint>

// Problem constants
#define NN      131072      // nodes
#define FF      512         // features
#define EE      2097152     // edges (2^21)
#define DA      16          // edge attr dim
#define NPOOL   65536       // pooled nodes
#define FP      256         // pooled features
#define NB      16384       // sort buckets (top 14 bits of key)
#define BKSHIFT 18          // key >> 18 = top 14 bits
#define SB      512         // max bucket size / sort block

// Output layout (elements, single concatenated array)
#define X_OFF   0ull
#define EI_OFF  16777216ull                              // 65536*256
#define EA_OFF  (EI_OFF + 2ull*EE)                       // 20971520
#define BP_OFF  (EA_OFF + (unsigned long long)EE*DA)     // 54525952

// ---------------- scratch (static device globals; no allocation) -------------
__device__ unsigned            g_keys[EE];     // 8 MB
__device__ unsigned long long  g_bkt[EE];      // 16 MB: (key<<32)|edge_idx
__device__ unsigned short     g_lrank[EE];     // 4 MB: in-bucket distinct rank
__device__ unsigned            g_cnt[NB];
__device__ unsigned            g_start[NB];
__device__ unsigned            g_cur[NB];
__device__ unsigned            g_dcnt[NB];
__device__ unsigned            g_doff[NB];
__device__ unsigned            g_totalU;
__device__ int                 g_is32;         // 1 if edge_index buffer is int32

// ---------------- kernels ----------------------------------------------------

__global__ void k_zero() {
    int i = blockIdx.x * blockDim.x + threadIdx.x;
    if (i < NB) { g_cnt[i] = 0; g_cur[i] = 0; }
    if (i == 0) g_is32 = 0;
}

// dtype sniff: int64 values < 2^31 => every high word is 0.
// Reads only first 512 int32 words (2 KB) — in bounds for both dtypes.
__global__ void k_detect(const int2* __restrict__ ei) {
    int t = threadIdx.x;                  // 256 threads
    if (ei[t].y != 0) atomicExch(&g_is32, 1);
}

// keys + histogram (branch on detected dtype; uniform across warp)
__global__ void k_keys_hist(const void* __restrict__ eiv) {
    int e = blockIdx.x * blockDim.x + threadIdx.x;
    if (e >= EE) return;
    unsigned r, c;
    if (g_is32) {
        const int* ei = (const int*)eiv;
        r = (unsigned)ei[e];
        c = (unsigned)ei[EE + e];
    } else {
        const long long* ei = (const long long*)eiv;
        r = (unsigned)ei[e];
        c = (unsigned)ei[EE + e];
    }
    unsigned key = ((r >> 1) << 16) | (c >> 1);
    g_keys[e] = key;
    atomicAdd(&g_cnt[key >> BKSHIFT], 1u);
}

// 16K exclusive scan, single block of 1024 threads
__global__ void k_scan16k(const unsigned* __restrict__ in, unsigned* __restrict__ out,
                          unsigned* total) {
    __shared__ unsigned s[1024];
    int tid = threadIdx.x;
    unsigned carry = 0;
    for (int ch = 0; ch < NB / 1024; ch++) {
        int i = ch * 1024 + tid;
        unsigned v = in[i];
        s[tid] = v;
        __syncthreads();
        for (int off = 1; off < 1024; off <<= 1) {
            unsigned t = (tid >= off) ? s[tid - off] : 0u;
            __syncthreads();
            s[tid] += t;
            __syncthreads();
        }
        out[i] = carry + s[tid] - v;   // exclusive
        unsigned tot = s[1023];
        __syncthreads();
        carry += tot;
    }
    if (tid == 0 && total) *total = carry;
}

// scatter into buckets
__global__ void k_scatter() {
    int e = blockIdx.x * blockDim.x + threadIdx.x;
    if (e >= EE) return;
    unsigned key = g_keys[e];
    unsigned b = key >> BKSHIFT;
    unsigned pos = g_start[b] + atomicAdd(&g_cur[b], 1u);
    g_bkt[pos] = ((unsigned long long)key << 32) | (unsigned)e;
}

// per-bucket bitonic sort + head-flag scan
__global__ __launch_bounds__(SB) void k_sort() {
    __shared__ unsigned long long s[SB];
    __shared__ unsigned sc[SB];
    int b = blockIdx.x;
    int tid = threadIdx.x;
    unsigned count = g_cnt[b];
    if (count == 0) { if (tid == 0) g_dcnt[b] = 0; return; }
    if (count > SB) count = SB;   // statistically impossible; safety clamp
    unsigned start = g_start[b];
    unsigned m = 1; while (m < count) m <<= 1;

    s[tid] = (tid < (int)count) ? g_bkt[start + tid] : 0xFFFFFFFFFFFFFFFFull;
    __syncthreads();
    for (unsigned k = 2; k <= m; k <<= 1) {
        for (unsigned j = k >> 1; j > 0; j >>= 1) {
            unsigned ixj = (unsigned)tid ^ j;
            if (ixj > (unsigned)tid && ixj < m) {
                unsigned long long a = s[tid], c = s[ixj];
                bool asc = (((unsigned)tid & k) == 0);
                if ((a > c) == asc) { s[tid] = c; s[ixj] = a; }
            }
            __syncthreads();
        }
    }
    // head flags + inclusive scan
    unsigned flag = 0;
    if (tid < (int)count)
        flag = (tid == 0) || ((unsigned)(s[tid] >> 32) != (unsigned)(s[tid - 1] >> 32));
    sc[tid] = flag;
    __syncthreads();
    for (int off = 1; off < SB; off <<= 1) {
        unsigned t = (tid >= off) ? sc[tid - off] : 0u;
        __syncthreads();
        sc[tid] += t;
        __syncthreads();
    }
    if (tid < (int)count) {
        g_bkt[start + tid]   = s[tid];
        g_lrank[start + tid] = (unsigned short)(sc[tid] - 1);
    }
    if (tid == 0) g_dcnt[b] = sc[count - 1];
}

// run heads: sum edge_attr over run, write pooled attr + pooled edge index
__global__ void k_runs(const float* __restrict__ ea, float* __restrict__ out) {
    int i = blockIdx.x * blockDim.x + threadIdx.x;
    if (i >= EE) return;
    unsigned long long p = g_bkt[i];
    unsigned key = (unsigned)(p >> 32);
    if (i > 0 && (unsigned)(g_bkt[i - 1] >> 32) == key) return; // not a run head
    unsigned rank = g_doff[key >> BKSHIFT] + (unsigned)g_lrank[i];

    float acc[DA];
#pragma unroll
    for (int d = 0; d < DA; d++) acc[d] = 0.f;
    int j = i;
    while (true) {
        unsigned idx = (unsigned)(p & 0xFFFFFFFFu);
        const float4* row = (const float4*)(ea + (size_t)idx * DA);
        float4 a = row[0], b2 = row[1], c = row[2], d4 = row[3];
        acc[0]  += a.x;  acc[1]  += a.y;  acc[2]  += a.z;  acc[3]  += a.w;
        acc[4]  += b2.x; acc[5]  += b2.y; acc[6]  += b2.z; acc[7]  += b2.w;
        acc[8]  += c.x;  acc[9]  += c.y;  acc[10] += c.z;  acc[11] += c.w;
        acc[12] += d4.x; acc[13] += d4.y; acc[14] += d4.z; acc[15] += d4.w;
        j++;
        if (j >= EE) break;
        p = g_bkt[j];
        if ((unsigned)(p >> 32) != key) break;
    }
    float* eao = out + EA_OFF + (size_t)rank * DA;
#pragma unroll
    for (int d = 0; d < DA; d++) eao[d] = acc[d];
    out[EI_OFF + rank]      = (float)(key >> 16);
    out[EI_OFF + EE + rank] = (float)(key & 0xFFFFu);
}

// padding for ranks >= U (fill_value = Np*Np -> (65536, 0), attr = 0)
__global__ void k_pad(float* __restrict__ out) {
    unsigned U = g_totalU;
    int r = blockIdx.x * blockDim.x + threadIdx.x;
    if (r >= EE || (unsigned)r < U) return;
    out[EI_OFF + r]      = 65536.0f;
    out[EI_OFF + EE + r] = 0.0f;
    float* eao = out + EA_OFF + (size_t)r * DA;
#pragma unroll
    for (int d = 0; d < DA; d++) eao[d] = 0.0f;
}

// 2x2 mean pool over contiguous (node, feature)
__global__ void k_xpool(const float* __restrict__ x, float* __restrict__ out) {
    int t = blockIdx.x * blockDim.x + threadIdx.x;
    if (t >= NPOOL * FP) return;
    int n = t >> 8;          // pooled node
    int f = t & 255;         // pooled feature
    const float2* r0 = (const float2*)(x + (size_t)(2 * n) * FF)     + f;
    const float2* r1 = (const float2*)(x + (size_t)(2 * n + 1) * FF) + f;
    float2 a = *r0, b = *r1;
    out[X_OFF + t] = 0.25f * ((a.x + a.y) + (b.x + b.y));
}

__global__ void k_batch(float* __restrict__ out) {
    int n = blockIdx.x * blockDim.x + threadIdx.x;
    if (n < NPOOL) out[BP_OFF + n] = (float)(n >> 10);
}

// ---------------- launch ------------------------------------------------------

extern "C" void kernel_launch(void* const* d_in, const int* in_sizes, int n_in,
                              void* d_out, int out_size) {
    const float* x  = (const float*)d_in[0];   // (N, F)
    const float* ea = (const float*)d_in[1];   // (E, DA)
    const void*  ei = d_in[2];                 // (2, E) int32 or int64
    float* out = (float*)d_out;

    unsigned* d_cnt;   cudaGetSymbolAddress((void**)&d_cnt,   g_cnt);
    unsigned* d_start; cudaGetSymbolAddress((void**)&d_start, g_start);
    unsigned* d_dcnt;  cudaGetSymbolAddress((void**)&d_dcnt,  g_dcnt);
    unsigned* d_doff;  cudaGetSymbolAddress((void**)&d_doff,  g_doff);
    unsigned* d_tot;   cudaGetSymbolAddress((void**)&d_tot,   g_totalU);

    k_zero<<<(NB + 255) / 256, 256>>>();
    k_detect<<<1, 256>>>((const int2*)ei);
    k_keys_hist<<<(EE + 255) / 256, 256>>>(ei);
    k_scan16k<<<1, 1024>>>(d_cnt, d_start, nullptr);
    k_scatter<<<(EE + 255) / 256, 256>>>();
    k_sort<<<NB, SB>>>();
    k_scan16k<<<1, 1024>>>(d_dcnt, d_doff, d_tot);
    k_runs<<<(EE + 255) / 256, 256>>>(ea, out);
    k_pad<<<(EE + 255) / 256, 256>>>(out);
    k_xpool<<<(NPOOL * FP + 255) / 256, 256>>>(x, out);
    k_batch<<<(NPOOL + 255) / 256, 256>>>(out);
}